// round 11
// baseline (speedup 1.0000x reference)
#include <cuda_runtime.h>
#include <cuda_bf16.h>
#include <cstdint>
#include <cstddef>

// Problem constants: B=16, H=8, L=512, D=64
#define BH   128
#define LEN  512
#define DIM  64
#define TI   128         // q-rows per CTA
#define NT   256         // 8 warps: each owns 16 rows, full n/k
#define NJT  8           // 512/64 j-tiles
#define PB   72          // bf16 smem pitch (144B rows)
#define NELEM (BH*LEN*DIM)

// smem layout (bytes)
// stage s (s=0,1) at s*STAGE_BYTES: KH +0, KL +9216, VH +18432, VL +27648
#define STAGE_BYTES 36864
#define OFF_Q   73728            // QH 18432 (128 x 72 bf16), QL at +18432
#define OFF_MC  110592           // 512 f32
#define OFF_RS  112640           // 128 f32 row sums
#define OFF_RI  113152           // 128 f32 reciprocals
#define SMEM_BYTES 113664

// pre-split bf16 hi/lo scratch for K and V (written by prologue kernel)
__device__ __nv_bfloat16 g_kh[NELEM];
__device__ __nv_bfloat16 g_kl[NELEM];
__device__ __nv_bfloat16 g_vh[NELEM];
__device__ __nv_bfloat16 g_vl[NELEM];

__device__ __forceinline__ uint32_t smem_u32(const void* p) {
    return (uint32_t)__cvta_generic_to_shared(p);
}
__device__ __forceinline__ void ldsm4(uint32_t* r, uint32_t a) {
    asm volatile("ldmatrix.sync.aligned.m8n8.x4.shared.b16 {%0,%1,%2,%3}, [%4];"
                 : "=r"(r[0]), "=r"(r[1]), "=r"(r[2]), "=r"(r[3]) : "r"(a));
}
__device__ __forceinline__ void ldsm4t(uint32_t* r, uint32_t a) {
    asm volatile("ldmatrix.sync.aligned.m8n8.x4.trans.shared.b16 {%0,%1,%2,%3}, [%4];"
                 : "=r"(r[0]), "=r"(r[1]), "=r"(r[2]), "=r"(r[3]) : "r"(a));
}
__device__ __forceinline__ void mma_bf16(float* c, const uint32_t* a, uint32_t b0, uint32_t b1) {
    asm volatile("mma.sync.aligned.m16n8k16.row.col.f32.bf16.bf16.f32 "
                 "{%0,%1,%2,%3}, {%4,%5,%6,%7}, {%8,%9}, {%0,%1,%2,%3};"
                 : "+f"(c[0]), "+f"(c[1]), "+f"(c[2]), "+f"(c[3])
                 : "r"(a[0]), "r"(a[1]), "r"(a[2]), "r"(a[3]), "r"(b0), "r"(b1));
}
__device__ __forceinline__ void split2(float x0, float x1, uint32_t& h, uint32_t& l) {
    __nv_bfloat16 h0 = __float2bfloat16(x0);
    __nv_bfloat16 h1 = __float2bfloat16(x1);
    __nv_bfloat16 l0 = __float2bfloat16(x0 - __bfloat162float(h0));
    __nv_bfloat16 l1 = __float2bfloat16(x1 - __bfloat162float(h1));
    __nv_bfloat162 hp = __nv_bfloat162(h0, h1);
    __nv_bfloat162 lp = __nv_bfloat162(l0, l1);
    h = *reinterpret_cast<uint32_t*>(&hp);
    l = *reinterpret_cast<uint32_t*>(&lp);
}
#define CP16(dst, src) \
    asm volatile("cp.async.cg.shared.global [%0], [%1], 16;" :: "r"(dst), "l"(src))
#define CP_COMMIT() asm volatile("cp.async.commit_group;")
#define CP_WAIT0()  asm volatile("cp.async.wait_group 0;")

// ---------------- prologue: fp32 -> bf16 hi/lo split (K and V) ----------------
__global__ void __launch_bounds__(256)
split2_kernel(const float* __restrict__ k,
              const float* __restrict__ v)
{
    const float* src = (blockIdx.y == 0) ? k : v;
    __nv_bfloat16* hi = (blockIdx.y == 0) ? g_kh : g_vh;
    __nv_bfloat16* lo = (blockIdx.y == 0) ? g_kl : g_vl;

    int i = blockIdx.x * 256 + threadIdx.x;       // 8-float chunk index
    float4 x0 = ((const float4*)src)[2 * i];
    float4 x1 = ((const float4*)src)[2 * i + 1];
    uint4 h, l;
    split2(x0.x, x0.y, h.x, l.x);
    split2(x0.z, x0.w, h.y, l.y);
    split2(x1.x, x1.y, h.z, l.z);
    split2(x1.z, x1.w, h.w, l.w);
    ((uint4*)hi)[i] = h;
    ((uint4*)lo)[i] = l;
}

// ---------------- main fused attention ----------------
__global__ void __launch_bounds__(NT, 2)
attn_tc_kernel(const float* __restrict__ q,
               const float* __restrict__ mask,
               float* __restrict__ out_o,
               float* __restrict__ out_attn)
{
    extern __shared__ char smc[];
    float* mc = (float*)(smc + OFF_MC);
    float* rsp = (float*)(smc + OFF_RS);
    float* rinv = (float*)(smc + OFF_RI);
    __nv_bfloat16* Qh = (__nv_bfloat16*)(smc + OFF_Q);
    __nv_bfloat16* Ql = (__nv_bfloat16*)(smc + OFF_Q + 18432);

    const int bh  = blockIdx.y;
    const int i0  = blockIdx.x * TI;
    const int b   = bh >> 3;              // H = 8
    const int tid = threadIdx.x;
    const int L   = tid & 31;
    const int w   = tid >> 5;             // warp 0..7 -> rows w*16..w*16+15
    const int g   = L >> 2;
    const int t   = L & 3;

    const uint32_t smB = smem_u32(smc);
    const uint32_t qhB = smB + OFF_Q;

    const __nv_bfloat16* kh_b = g_kh + (size_t)bh * LEN * DIM;
    const __nv_bfloat16* kl_b = g_kl + (size_t)bh * LEN * DIM;
    const __nv_bfloat16* vh_b = g_vh + (size_t)bh * LEN * DIM;
    const __nv_bfloat16* vl_b = g_vl + (size_t)bh * LEN * DIM;

    // per-thread cp.async addressing for K/V tiles
    const int cprow0 = tid >> 3;              // rows tid/8 and tid/8+32
    const int cpch   = (tid & 7) * 8;
    const uint32_t cpdoff0 = (uint32_t)(cprow0 * PB + cpch) * 2;
    const uint32_t cpdoff1 = (uint32_t)((cprow0 + 32) * PB + cpch) * 2;

    // issue tile 0 into stage 0 first (loads fly under Q split below)
    {
        int soff0 = cprow0 * DIM + cpch;
        int soff1 = (cprow0 + 32) * DIM + cpch;
        uint32_t s0 = smB;
        CP16(s0 + cpdoff0,          kh_b + soff0);
        CP16(s0 + cpdoff1,          kh_b + soff1);
        CP16(s0 + 9216  + cpdoff0,  kl_b + soff0);
        CP16(s0 + 9216  + cpdoff1,  kl_b + soff1);
        CP16(s0 + 18432 + cpdoff0,  vh_b + soff0);
        CP16(s0 + 18432 + cpdoff1,  vh_b + soff1);
        CP16(s0 + 27648 + cpdoff0,  vl_b + soff0);
        CP16(s0 + 27648 + cpdoff1,  vl_b + soff1);
        CP_COMMIT();
    }

    // column mask term: 0 or 1e9
    for (int j = tid; j < LEN; j += NT) {
        float mv = mask[b * LEN + j];
        mc[j] = (mv == -10000.0f) ? 1e9f : mv;
    }

    // inline Q split: 128x64 fp32 -> bf16 hi/lo in smem
    {
        const float* qb = q + ((size_t)bh * LEN + i0) * DIM;
        #pragma unroll
        for (int it = 0; it < 8; it++) {
            int lin = it * NT + tid;             // 0..2047 float4 chunks
            int row = lin >> 4;
            int c4  = (lin & 15) * 4;
            float4 x = *(const float4*)(qb + row * DIM + c4);
            uint32_t h01, l01, h23, l23;
            split2(x.x, x.y, h01, l01);
            split2(x.z, x.w, h23, l23);
            *(uint32_t*)&Qh[row * PB + c4]     = h01;
            *(uint32_t*)&Qh[row * PB + c4 + 2] = h23;
            *(uint32_t*)&Ql[row * PB + c4]     = l01;
            *(uint32_t*)&Ql[row * PB + c4 + 2] = l23;
        }
    }
    CP_WAIT0();
    __syncthreads();

    float oacc[8][4];
    #pragma unroll
    for (int n = 0; n < 8; n++)
        #pragma unroll
        for (int c = 0; c < 4; c++) oacc[n][c] = 0.0f;
    float rs0 = 0.0f, rs1 = 0.0f;

    const int r0l = w * 16 + g;
    const int r1l = r0l + 8;

    // addressing
    const int arow   = w * 16 + (L & 15);         // Q A-frag row
    const int acol   = (L >> 4) * 8;
    const int b1row  = ((L >> 4) & 1) * 8 + (L & 7);   // K B-frag
    const int b1col  = ((L >> 3) & 1) * 8;
    const int b2row  = ((L >> 3) & 1) * 8 + (L & 7);   // V (trans) B-frag
    const int b2colh = (L >> 4) * 8;

    const bool rowM0 = (mc[i0 + r0l] != 0.0f);
    const bool rowM1 = (mc[i0 + r1l] != 0.0f);

    float* ab = out_attn ? out_attn + ((size_t)bh * LEN + i0) * LEN : nullptr;

    for (int jt = 0; jt < NJT; jt++) {
        const uint32_t stB = smB + (uint32_t)(jt & 1) * STAGE_BYTES;

        // prefetch next tile into the other stage
        if (jt + 1 < NJT) {
            const int j1 = (jt + 1) * 64;
            uint32_t s1 = smB + (uint32_t)((jt + 1) & 1) * STAGE_BYTES;
            int soff0 = (j1 + cprow0) * DIM + cpch;
            int soff1 = (j1 + cprow0 + 32) * DIM + cpch;
            CP16(s1 + cpdoff0,          kh_b + soff0);
            CP16(s1 + cpdoff1,          kh_b + soff1);
            CP16(s1 + 9216  + cpdoff0,  kl_b + soff0);
            CP16(s1 + 9216  + cpdoff1,  kl_b + soff1);
            CP16(s1 + 18432 + cpdoff0,  vh_b + soff0);
            CP16(s1 + 18432 + cpdoff1,  vh_b + soff1);
            CP16(s1 + 27648 + cpdoff0,  vl_b + soff0);
            CP16(s1 + 27648 + cpdoff1,  vl_b + soff1);
            CP_COMMIT();
        }

        // ---- GEMM1: S(16x64 per warp) = Q.K^T, 3-pass bf16 split ----
        float sacc[8][4];
        #pragma unroll
        for (int n = 0; n < 8; n++)
            #pragma unroll
            for (int c = 0; c < 4; c++) sacc[n][c] = 0.0f;

        #pragma unroll
        for (int ks = 0; ks < 4; ks++) {
            uint32_t qaddr = qhB + (uint32_t)(arow * PB + ks * 16 + acol) * 2;
            uint32_t qh4[4], ql4[4];
            ldsm4(qh4, qaddr);
            ldsm4(ql4, qaddr + 18432);
            #pragma unroll
            for (int jb = 0; jb < 4; jb++) {
                uint32_t addr = stB + (uint32_t)((b1row + jb * 16) * PB + ks * 16 + b1col) * 2;
                uint32_t bh4[4], bl4[4];
                ldsm4(bh4, addr);
                ldsm4(bl4, addr + 9216);
                mma_bf16(sacc[2 * jb],     qh4, bh4[0], bh4[1]);
                mma_bf16(sacc[2 * jb + 1], qh4, bh4[2], bh4[3]);
                mma_bf16(sacc[2 * jb],     qh4, bl4[0], bl4[1]);
                mma_bf16(sacc[2 * jb + 1], qh4, bl4[2], bl4[3]);
                mma_bf16(sacc[2 * jb],     ql4, bh4[0], bh4[1]);
                mma_bf16(sacc[2 * jb + 1], ql4, bh4[2], bh4[3]);
            }
        }

        // ---- interleaved epilogue + GEMM2, per 16-col (=16-k) chunk ----
        const int j0 = jt * 64;
        #pragma unroll
        for (int ks2 = 0; ks2 < 4; ks2++) {
            uint32_t ah[4], al[4];
            #pragma unroll
            for (int nb2 = 0; nb2 < 2; nb2++) {
                int nb = 2 * ks2 + nb2;
                int lcol = nb * 8 + 2 * t;
                int jj = j0 + lcol;
                float mj0 = mc[jj], mj1 = mc[jj + 1];
                float u0 = (mj0 == 0.0f) ? 1.0f : 0.0f;
                float u1 = (mj1 == 0.0f) ? 1.0f : 0.0f;
                float e00 = rowM0 ? u0 : __expf(fmaf(sacc[nb][0], 0.125f, -mj0));
                float e01 = rowM0 ? u1 : __expf(fmaf(sacc[nb][1], 0.125f, -mj1));
                float e10 = rowM1 ? u0 : __expf(fmaf(sacc[nb][2], 0.125f, -mj0));
                float e11 = rowM1 ? u1 : __expf(fmaf(sacc[nb][3], 0.125f, -mj1));
                rs0 += e00 + e01;
                rs1 += e10 + e11;
                if (ab) {
                    *(float2*)&ab[(size_t)r0l * LEN + jj] = make_float2(e00, e01);
                    *(float2*)&ab[(size_t)r1l * LEN + jj] = make_float2(e10, e11);
                }
                split2(e00, e01, ah[2 * nb2],     al[2 * nb2]);
                split2(e10, e11, ah[2 * nb2 + 1], al[2 * nb2 + 1]);
            }
            #pragma unroll
            for (int dc = 0; dc < 4; dc++) {
                uint32_t vaddr = stB + 18432 +
                    (uint32_t)((ks2 * 16 + b2row) * PB + dc * 16 + b2colh) * 2;
                uint32_t vh4[4], vl4[4];
                ldsm4t(vh4, vaddr);
                ldsm4t(vl4, vaddr + 9216);
                mma_bf16(oacc[2 * dc],     ah, vh4[0], vh4[1]);
                mma_bf16(oacc[2 * dc + 1], ah, vh4[2], vh4[3]);
                mma_bf16(oacc[2 * dc],     ah, vl4[0], vl4[1]);
                mma_bf16(oacc[2 * dc + 1], ah, vl4[2], vl4[3]);
                mma_bf16(oacc[2 * dc],     al, vh4[0], vh4[1]);
                mma_bf16(oacc[2 * dc + 1], al, vh4[2], vh4[3]);
            }
        }

        CP_WAIT0();       // next tile's loads done (overlapped with compute)
        __syncthreads();  // all warps done with this stage
    }

    // ---- rowsum reduction across the 4 t-lanes (full row per warp) ----
    rs0 += __shfl_xor_sync(0xffffffffu, rs0, 1);
    rs0 += __shfl_xor_sync(0xffffffffu, rs0, 2);
    rs1 += __shfl_xor_sync(0xffffffffu, rs1, 1);
    rs1 += __shfl_xor_sync(0xffffffffu, rs1, 2);
    if (t == 0) {
        rsp[r0l] = rs0;
        rsp[r1l] = rs1;
    }
    __syncthreads();
    if (tid < TI) rinv[tid] = 1.0f / rsp[tid];
    __syncthreads();

    // ---- O written straight from registers (each warp owns full k) ----
    if (out_o) {
        float inv0 = rinv[r0l];
        float inv1 = rinv[r1l];
        float* ob0 = out_o + ((size_t)bh * LEN + i0 + r0l) * DIM;
        float* ob1 = out_o + ((size_t)bh * LEN + i0 + r1l) * DIM;
        #pragma unroll
        for (int nb = 0; nb < 8; nb++) {
            int dcol = nb * 8 + 2 * t;
            *(float2*)&ob0[dcol] = make_float2(oacc[nb][0] * inv0, oacc[nb][1] * inv0);
            *(float2*)&ob1[dcol] = make_float2(oacc[nb][2] * inv1, oacc[nb][3] * inv1);
        }
    }

    // ---- normalize attn in place (CTA just wrote it; L2-hot) ----
    if (ab) {
        #pragma unroll 4
        for (int i4 = tid; i4 < TI * (LEN / 4); i4 += NT) {
            int row = i4 >> 7;
            int col = (i4 & 127) * 4;
            float inv = rinv[row];
            float4 e = *(const float4*)&ab[(size_t)row * LEN + col];
            e.x *= inv; e.y *= inv; e.z *= inv; e.w *= inv;
            *(float4*)&ab[(size_t)row * LEN + col] = e;
        }
    }
}

extern "C" void kernel_launch(void* const* d_in, const int* in_sizes, int n_in,
                              void* d_out, int out_size)
{
    const float* q    = (const float*)d_in[0];
    const float* k    = (const float*)d_in[1];
    const float* v    = (const float*)d_in[2];
    const float* mask = (const float*)d_in[3];

    const long long O_ELEMS = (long long)BH * LEN * DIM;   // 4194304
    const long long A_ELEMS = (long long)BH * LEN * LEN;   // 33554432

    float* out = (float*)d_out;
    float* o_ptr = nullptr;
    float* a_ptr = nullptr;
    if ((long long)out_size >= O_ELEMS + A_ELEMS) {
        o_ptr = out;
        a_ptr = out + O_ELEMS;
    } else if ((long long)out_size == A_ELEMS) {
        a_ptr = out;
    } else {
        o_ptr = out;
    }

    dim3 sgrid(NELEM / 8 / 256, 2);
    split2_kernel<<<sgrid, 256>>>(k, v);

    cudaFuncSetAttribute(attn_tc_kernel,
                         cudaFuncAttributeMaxDynamicSharedMemorySize, SMEM_BYTES);

    dim3 grid(LEN / TI, BH);   // (4, 128) = 512 CTAs
    attn_tc_kernel<<<grid, NT, SMEM_BYTES>>>(q, mask, o_ptr, a_ptr);
}

// round 12
// speedup vs baseline: 1.1476x; 1.1476x over previous
#include <cuda_runtime.h>
#include <cuda_bf16.h>
#include <cstdint>
#include <cstddef>

// Problem constants: B=16, H=8, L=512, D=64
#define BH   128
#define LEN  512
#define DIM  64
#define TI   64          // q-rows per CTA
#define NT   256         // 8 warps: 4 row-groups (wi) x 2 k-groups (wj)
#define NJT  8           // 512/64 j-tiles
#define PB   72          // bf16 smem pitch (144B rows)
#define NELEM (BH*LEN*DIM)

// smem layout (bytes)
// stage s (s=0,1) at s*STAGE_BYTES: KH +0, KL +9216, VH +18432, VL +27648
#define STAGE_BYTES 36864
#define OFF_Q   73728            // QH 9216 (64 x 72 bf16), QL at +9216
#define OFF_MC  92160            // 512 f32
#define OFF_RS  94208            // 64 x 2 f32
#define OFF_RI  94720            // 64 f32
#define SMEM_BYTES 94976
// O-reduction buffer reuses dead stage-0 after the loop: 2*64*66*4 = 33792 B
#define OBP 66

// pre-split bf16 hi/lo scratch for K and V (written by prologue kernel)
__device__ __nv_bfloat16 g_kh[NELEM];
__device__ __nv_bfloat16 g_kl[NELEM];
__device__ __nv_bfloat16 g_vh[NELEM];
__device__ __nv_bfloat16 g_vl[NELEM];

__device__ __forceinline__ uint32_t smem_u32(const void* p) {
    return (uint32_t)__cvta_generic_to_shared(p);
}
__device__ __forceinline__ void ldsm4(uint32_t* r, uint32_t a) {
    asm volatile("ldmatrix.sync.aligned.m8n8.x4.shared.b16 {%0,%1,%2,%3}, [%4];"
                 : "=r"(r[0]), "=r"(r[1]), "=r"(r[2]), "=r"(r[3]) : "r"(a));
}
__device__ __forceinline__ void ldsm4t(uint32_t* r, uint32_t a) {
    asm volatile("ldmatrix.sync.aligned.m8n8.x4.trans.shared.b16 {%0,%1,%2,%3}, [%4];"
                 : "=r"(r[0]), "=r"(r[1]), "=r"(r[2]), "=r"(r[3]) : "r"(a));
}
__device__ __forceinline__ void mma_bf16(float* c, const uint32_t* a, uint32_t b0, uint32_t b1) {
    asm volatile("mma.sync.aligned.m16n8k16.row.col.f32.bf16.bf16.f32 "
                 "{%0,%1,%2,%3}, {%4,%5,%6,%7}, {%8,%9}, {%0,%1,%2,%3};"
                 : "+f"(c[0]), "+f"(c[1]), "+f"(c[2]), "+f"(c[3])
                 : "r"(a[0]), "r"(a[1]), "r"(a[2]), "r"(a[3]), "r"(b0), "r"(b1));
}
__device__ __forceinline__ void split2(float x0, float x1, uint32_t& h, uint32_t& l) {
    __nv_bfloat16 h0 = __float2bfloat16(x0);
    __nv_bfloat16 h1 = __float2bfloat16(x1);
    __nv_bfloat16 l0 = __float2bfloat16(x0 - __bfloat162float(h0));
    __nv_bfloat16 l1 = __float2bfloat16(x1 - __bfloat162float(h1));
    __nv_bfloat162 hp = __nv_bfloat162(h0, h1);
    __nv_bfloat162 lp = __nv_bfloat162(l0, l1);
    h = *reinterpret_cast<uint32_t*>(&hp);
    l = *reinterpret_cast<uint32_t*>(&lp);
}
#define CP16(dst, src) \
    asm volatile("cp.async.cg.shared.global [%0], [%1], 16;" :: "r"(dst), "l"(src))
#define CP_COMMIT() asm volatile("cp.async.commit_group;")
#define CP_WAIT0()  asm volatile("cp.async.wait_group 0;")

// ---------------- prologue: fp32 -> bf16 hi/lo split (K and V) ----------------
__global__ void __launch_bounds__(256)
split2_kernel(const float* __restrict__ k,
              const float* __restrict__ v)
{
    const float* src = (blockIdx.y == 0) ? k : v;
    __nv_bfloat16* hi = (blockIdx.y == 0) ? g_kh : g_vh;
    __nv_bfloat16* lo = (blockIdx.y == 0) ? g_kl : g_vl;

    int i = blockIdx.x * 256 + threadIdx.x;       // 8-float chunk index
    float4 x0 = ((const float4*)src)[2 * i];
    float4 x1 = ((const float4*)src)[2 * i + 1];
    uint4 h, l;
    split2(x0.x, x0.y, h.x, l.x);
    split2(x0.z, x0.w, h.y, l.y);
    split2(x1.x, x1.y, h.z, l.z);
    split2(x1.z, x1.w, h.w, l.w);
    ((uint4*)hi)[i] = h;
    ((uint4*)lo)[i] = l;
}

// ---------------- main fused attention ----------------
__global__ void __launch_bounds__(NT, 2)
attn_tc_kernel(const float* __restrict__ q,
               const float* __restrict__ mask,
               float* __restrict__ out_o,
               float* __restrict__ out_attn)
{
    extern __shared__ char smc[];
    float* mc = (float*)(smc + OFF_MC);
    float (*rsp)[2] = (float (*)[2])(smc + OFF_RS);
    float* rinv = (float*)(smc + OFF_RI);
    float* Ob = (float*)smc;              // reuses stage 0 after the loop
    __nv_bfloat16* Qh = (__nv_bfloat16*)(smc + OFF_Q);
    __nv_bfloat16* Ql = (__nv_bfloat16*)(smc + OFF_Q + 9216);

    const int bh  = blockIdx.y;
    const int i0  = blockIdx.x * TI;
    const int b   = bh >> 3;              // H = 8
    const int tid = threadIdx.x;
    const int L   = tid & 31;
    const int w   = tid >> 5;             // warp 0..7
    const int wi  = w & 3;                // 16-row group
    const int wj  = w >> 2;               // 0..1 -> 32-col (=k) group
    const int g   = L >> 2;
    const int t   = L & 3;

    const uint32_t smB = smem_u32(smc);
    const uint32_t qhB = smB + OFF_Q;

    const __nv_bfloat16* kh_b = g_kh + (size_t)bh * LEN * DIM;
    const __nv_bfloat16* kl_b = g_kl + (size_t)bh * LEN * DIM;
    const __nv_bfloat16* vh_b = g_vh + (size_t)bh * LEN * DIM;
    const __nv_bfloat16* vl_b = g_vl + (size_t)bh * LEN * DIM;

    // per-thread cp.async addressing for K/V tiles
    const int cprow0 = tid >> 3;              // rows tid/8 and tid/8+32
    const int cpch   = (tid & 7) * 8;
    const uint32_t cpdoff0 = (uint32_t)(cprow0 * PB + cpch) * 2;
    const uint32_t cpdoff1 = (uint32_t)((cprow0 + 32) * PB + cpch) * 2;

    // issue tile 0 into stage 0 first (loads fly under Q split below)
    {
        int soff0 = cprow0 * DIM + cpch;
        int soff1 = (cprow0 + 32) * DIM + cpch;
        uint32_t s0 = smB;
        CP16(s0 + cpdoff0,          kh_b + soff0);
        CP16(s0 + cpdoff1,          kh_b + soff1);
        CP16(s0 + 9216  + cpdoff0,  kl_b + soff0);
        CP16(s0 + 9216  + cpdoff1,  kl_b + soff1);
        CP16(s0 + 18432 + cpdoff0,  vh_b + soff0);
        CP16(s0 + 18432 + cpdoff1,  vh_b + soff1);
        CP16(s0 + 27648 + cpdoff0,  vl_b + soff0);
        CP16(s0 + 27648 + cpdoff1,  vl_b + soff1);
        CP_COMMIT();
    }

    // column mask term: 0 or 1e9
    for (int j = tid; j < LEN; j += NT) {
        float mv = mask[b * LEN + j];
        mc[j] = (mv == -10000.0f) ? 1e9f : mv;
    }

    // inline Q split: 64x64 fp32 -> bf16 hi/lo in smem
    {
        const float* qb = q + ((size_t)bh * LEN + i0) * DIM;
        #pragma unroll
        for (int it = 0; it < 4; it++) {
            int lin = it * NT + tid;             // 0..1023 float4 chunks
            int row = lin >> 4;
            int c4  = (lin & 15) * 4;
            float4 x = *(const float4*)(qb + row * DIM + c4);
            uint32_t h01, l01, h23, l23;
            split2(x.x, x.y, h01, l01);
            split2(x.z, x.w, h23, l23);
            *(uint32_t*)&Qh[row * PB + c4]     = h01;
            *(uint32_t*)&Qh[row * PB + c4 + 2] = h23;
            *(uint32_t*)&Ql[row * PB + c4]     = l01;
            *(uint32_t*)&Ql[row * PB + c4 + 2] = l23;
        }
    }
    CP_WAIT0();
    __syncthreads();

    float oacc[8][4];
    #pragma unroll
    for (int n = 0; n < 8; n++)
        #pragma unroll
        for (int c = 0; c < 4; c++) oacc[n][c] = 0.0f;
    float rs0 = 0.0f, rs1 = 0.0f;

    const int r0l = wi * 16 + g;
    const int r1l = r0l + 8;

    // Q A-frag addressing
    const int arow = wi * 16 + (L & 15);
    const int acol = (L >> 4) * 8;
    // GEMM1 B (K): row base within warp's 32-j group
    const int b1rowb = wj * 32 + ((L >> 4) & 1) * 8 + (L & 7);
    const int b1col  = ((L >> 3) & 1) * 8;
    // GEMM2 B (V, trans)
    const int b2rowb = wj * 32 + ((L >> 3) & 1) * 8 + (L & 7);
    const int b2colh = (L >> 4) * 8;

    // persistent Q-hi fragments (Q smem never overwritten during the loop)
    uint32_t qh_p[4][4];
    #pragma unroll
    for (int ks = 0; ks < 4; ks++) {
        uint32_t qaddr = qhB + (uint32_t)(arow * PB + ks * 16 + acol) * 2;
        ldsm4(qh_p[ks], qaddr);
    }

    const bool rowM0 = (mc[i0 + r0l] != 0.0f);
    const bool rowM1 = (mc[i0 + r1l] != 0.0f);

    float* ab = out_attn ? out_attn + ((size_t)bh * LEN + i0) * LEN : nullptr;

    for (int jt = 0; jt < NJT; jt++) {
        const uint32_t stB = smB + (uint32_t)(jt & 1) * STAGE_BYTES;

        // prefetch next tile into the other stage
        if (jt + 1 < NJT) {
            const int j1 = (jt + 1) * 64;
            uint32_t s1 = smB + (uint32_t)((jt + 1) & 1) * STAGE_BYTES;
            int soff0 = (j1 + cprow0) * DIM + cpch;
            int soff1 = (j1 + cprow0 + 32) * DIM + cpch;
            CP16(s1 + cpdoff0,          kh_b + soff0);
            CP16(s1 + cpdoff1,          kh_b + soff1);
            CP16(s1 + 9216  + cpdoff0,  kl_b + soff0);
            CP16(s1 + 9216  + cpdoff1,  kl_b + soff1);
            CP16(s1 + 18432 + cpdoff0,  vh_b + soff0);
            CP16(s1 + 18432 + cpdoff1,  vh_b + soff1);
            CP16(s1 + 27648 + cpdoff0,  vl_b + soff0);
            CP16(s1 + 27648 + cpdoff1,  vl_b + soff1);
            CP_COMMIT();
        }

        // ---- GEMM1: S(16x32 per warp) = Q.K^T, 3-pass bf16 split ----
        float sacc[4][4];
        #pragma unroll
        for (int n = 0; n < 4; n++)
            #pragma unroll
            for (int c = 0; c < 4; c++) sacc[n][c] = 0.0f;

        #pragma unroll
        for (int ks = 0; ks < 4; ks++) {
            uint32_t ql4[4];
            ldsm4(ql4, qhB + 9216 + (uint32_t)(arow * PB + ks * 16 + acol) * 2);
            #pragma unroll
            for (int jb = 0; jb < 2; jb++) {
                uint32_t addr = stB + (uint32_t)((b1rowb + jb * 16) * PB + ks * 16 + b1col) * 2;
                uint32_t bh4[4], bl4[4];
                ldsm4(bh4, addr);
                ldsm4(bl4, addr + 9216);
                mma_bf16(sacc[2 * jb],     qh_p[ks], bh4[0], bh4[1]);
                mma_bf16(sacc[2 * jb + 1], qh_p[ks], bh4[2], bh4[3]);
                mma_bf16(sacc[2 * jb],     qh_p[ks], bl4[0], bl4[1]);
                mma_bf16(sacc[2 * jb + 1], qh_p[ks], bl4[2], bl4[3]);
                mma_bf16(sacc[2 * jb],     ql4, bh4[0], bh4[1]);
                mma_bf16(sacc[2 * jb + 1], ql4, bh4[2], bh4[3]);
            }
        }

        // ---- interleaved epilogue + GEMM2, per 16-k chunk ----
        const int j0 = jt * 64;
        #pragma unroll
        for (int ks2 = 0; ks2 < 2; ks2++) {
            uint32_t ah[4], al[4];
            #pragma unroll
            for (int nb2 = 0; nb2 < 2; nb2++) {
                int nb = 2 * ks2 + nb2;
                int lcol = wj * 32 + nb * 8 + 2 * t;
                int jj = j0 + lcol;
                float mj0 = mc[jj], mj1 = mc[jj + 1];
                float u0 = (mj0 == 0.0f) ? 1.0f : 0.0f;
                float u1 = (mj1 == 0.0f) ? 1.0f : 0.0f;
                float e00 = rowM0 ? u0 : __expf(fmaf(sacc[nb][0], 0.125f, -mj0));
                float e01 = rowM0 ? u1 : __expf(fmaf(sacc[nb][1], 0.125f, -mj1));
                float e10 = rowM1 ? u0 : __expf(fmaf(sacc[nb][2], 0.125f, -mj0));
                float e11 = rowM1 ? u1 : __expf(fmaf(sacc[nb][3], 0.125f, -mj1));
                rs0 += e00 + e01;
                rs1 += e10 + e11;
                if (ab) {
                    *(float2*)&ab[(size_t)r0l * LEN + jj] = make_float2(e00, e01);
                    *(float2*)&ab[(size_t)r1l * LEN + jj] = make_float2(e10, e11);
                }
                split2(e00, e01, ah[2 * nb2],     al[2 * nb2]);
                split2(e10, e11, ah[2 * nb2 + 1], al[2 * nb2 + 1]);
            }
            #pragma unroll
            for (int dc = 0; dc < 4; dc++) {
                uint32_t vaddr = stB + 18432 +
                    (uint32_t)((b2rowb + ks2 * 16) * PB + dc * 16 + b2colh) * 2;
                uint32_t vh4[4], vl4[4];
                ldsm4t(vh4, vaddr);
                ldsm4t(vl4, vaddr + 9216);
                mma_bf16(oacc[2 * dc],     ah, vh4[0], vh4[1]);
                mma_bf16(oacc[2 * dc + 1], ah, vh4[2], vh4[3]);
                mma_bf16(oacc[2 * dc],     ah, vl4[0], vl4[1]);
                mma_bf16(oacc[2 * dc + 1], ah, vl4[2], vl4[3]);
                mma_bf16(oacc[2 * dc],     al, vh4[0], vh4[1]);
                mma_bf16(oacc[2 * dc + 1], al, vh4[2], vh4[3]);
            }
        }

        CP_WAIT0();       // next tile's loads done (overlapped with compute)
        __syncthreads();  // all warps done with this stage
    }

    // ---- rowsum reduction across t-lanes then across the 2 wj groups ----
    rs0 += __shfl_xor_sync(0xffffffffu, rs0, 1);
    rs0 += __shfl_xor_sync(0xffffffffu, rs0, 2);
    rs1 += __shfl_xor_sync(0xffffffffu, rs1, 1);
    rs1 += __shfl_xor_sync(0xffffffffu, rs1, 2);
    if (t == 0) {
        rsp[r0l][wj] = rs0;
        rsp[r1l][wj] = rs1;
    }
    // dump partial O into the (now dead) stage-0 region
    #pragma unroll
    for (int nb = 0; nb < 8; nb++) {
        int col = nb * 8 + 2 * t;
        *(float2*)&Ob[wj * (64 * OBP) + r0l * OBP + col] = make_float2(oacc[nb][0], oacc[nb][1]);
        *(float2*)&Ob[wj * (64 * OBP) + r1l * OBP + col] = make_float2(oacc[nb][2], oacc[nb][3]);
    }
    __syncthreads();

    if (tid < TI)
        rinv[tid] = 1.0f / (rsp[tid][0] + rsp[tid][1]);
    __syncthreads();

    // ---- O reduce across 2 k-slices + write ----
    if (out_o) {
        #pragma unroll
        for (int rr = 0; rr < 2; rr++) {
            int row = rr * 32 + (tid >> 3);
            int c8  = (tid & 7) * 8;
            float s[8];
            #pragma unroll
            for (int i = 0; i < 8; i++)
                s[i] = Ob[row * OBP + c8 + i] + Ob[64 * OBP + row * OBP + c8 + i];
            float inv = rinv[row];
            float* ob = out_o + ((size_t)bh * LEN + i0 + row) * DIM + c8;
            *(float4*)ob       = make_float4(s[0] * inv, s[1] * inv, s[2] * inv, s[3] * inv);
            *(float4*)(ob + 4) = make_float4(s[4] * inv, s[5] * inv, s[6] * inv, s[7] * inv);
        }
    }

    // ---- normalize attn in place (CTA just wrote it; L2-hot) ----
    if (ab) {
        #pragma unroll 4
        for (int i4 = tid; i4 < TI * (LEN / 4); i4 += NT) {
            int row = i4 >> 7;
            int col = (i4 & 127) * 4;
            float inv = rinv[row];
            float4 e = *(const float4*)&ab[(size_t)row * LEN + col];
            e.x *= inv; e.y *= inv; e.z *= inv; e.w *= inv;
            *(float4*)&ab[(size_t)row * LEN + col] = e;
        }
    }
}

extern "C" void kernel_launch(void* const* d_in, const int* in_sizes, int n_in,
                              void* d_out, int out_size)
{
    const float* q    = (const float*)d_in[0];
    const float* k    = (const float*)d_in[1];
    const float* v    = (const float*)d_in[2];
    const float* mask = (const float*)d_in[3];

    const long long O_ELEMS = (long long)BH * LEN * DIM;   // 4194304
    const long long A_ELEMS = (long long)BH * LEN * LEN;   // 33554432

    float* out = (float*)d_out;
    float* o_ptr = nullptr;
    float* a_ptr = nullptr;
    if ((long long)out_size >= O_ELEMS + A_ELEMS) {
        o_ptr = out;
        a_ptr = out + O_ELEMS;
    } else if ((long long)out_size == A_ELEMS) {
        a_ptr = out;
    } else {
        o_ptr = out;
    }

    dim3 sgrid(NELEM / 8 / 256, 2);
    split2_kernel<<<sgrid, 256>>>(k, v);

    cudaFuncSetAttribute(attn_tc_kernel,
                         cudaFuncAttributeMaxDynamicSharedMemorySize, SMEM_BYTES);

    dim3 grid(LEN / TI, BH);   // (8, 128) = 1024 CTAs
    attn_tc_kernel<<<grid, NT, SMEM_BYTES>>>(q, mask, o_ptr, a_ptr);
}

// round 13
// speedup vs baseline: 1.5068x; 1.3129x over previous
#include <cuda_runtime.h>
#include <cuda_fp16.h>
#include <cstdint>
#include <cstddef>

// Problem constants: B=16, H=8, L=512, D=64
#define BH   128
#define LEN  512
#define DIM  64
#define TI   64          // q-rows per CTA
#define NT   256         // 8 warps: 4 row-groups (wi) x 2 k-groups (wj)
#define NJT  8           // 512/64 j-tiles
#define PB   72          // fp16 smem pitch (144B rows)
#define NELEM (BH*LEN*DIM)

// smem layout (bytes)
// stage s (s=0,1) at s*STAGE_BYTES: K +0 (9216), V +9216
#define STAGE_BYTES 18432
#define OFF_Q   36864            // Q fp16: 64 x 72 = 9216 B
#define OFF_MC  46080            // 512 f32
#define OFF_RS  48128            // 64 x 2 f32
#define OFF_RI  48640            // 64 f32
#define SMEM_BYTES 48896
// O-reduction buffer reuses dead stage region after the loop: 2*64*66*4 = 33792 B
#define OBP 66

// fp16 scratch for K and V (written by prologue kernel)
__device__ __half g_k[NELEM];
__device__ __half g_v[NELEM];

__device__ __forceinline__ uint32_t smem_u32(const void* p) {
    return (uint32_t)__cvta_generic_to_shared(p);
}
__device__ __forceinline__ void ldsm4(uint32_t* r, uint32_t a) {
    asm volatile("ldmatrix.sync.aligned.m8n8.x4.shared.b16 {%0,%1,%2,%3}, [%4];"
                 : "=r"(r[0]), "=r"(r[1]), "=r"(r[2]), "=r"(r[3]) : "r"(a));
}
__device__ __forceinline__ void ldsm4t(uint32_t* r, uint32_t a) {
    asm volatile("ldmatrix.sync.aligned.m8n8.x4.trans.shared.b16 {%0,%1,%2,%3}, [%4];"
                 : "=r"(r[0]), "=r"(r[1]), "=r"(r[2]), "=r"(r[3]) : "r"(a));
}
__device__ __forceinline__ void mma_f16(float* c, const uint32_t* a, uint32_t b0, uint32_t b1) {
    asm volatile("mma.sync.aligned.m16n8k16.row.col.f32.f16.f16.f32 "
                 "{%0,%1,%2,%3}, {%4,%5,%6,%7}, {%8,%9}, {%0,%1,%2,%3};"
                 : "+f"(c[0]), "+f"(c[1]), "+f"(c[2]), "+f"(c[3])
                 : "r"(a[0]), "r"(a[1]), "r"(a[2]), "r"(a[3]), "r"(b0), "r"(b1));
}
__device__ __forceinline__ uint32_t pack_h2(float x0, float x1) {
    __half2 h = __floats2half2_rn(x0, x1);   // .x = x0 (low), .y = x1 (high)
    return *reinterpret_cast<uint32_t*>(&h);
}
#define CP16(dst, src) \
    asm volatile("cp.async.cg.shared.global [%0], [%1], 16;" :: "r"(dst), "l"(src))
#define CP_COMMIT() asm volatile("cp.async.commit_group;")
#define CP_WAIT0()  asm volatile("cp.async.wait_group 0;")

// ---------------- prologue: fp32 -> fp16 convert (K and V) ----------------
__global__ void __launch_bounds__(256)
cvt_kernel(const float* __restrict__ k,
           const float* __restrict__ v)
{
    const float* src = (blockIdx.y == 0) ? k : v;
    __half* dst = (blockIdx.y == 0) ? g_k : g_v;

    int i = blockIdx.x * 256 + threadIdx.x;       // 8-float chunk index
    float4 x0 = ((const float4*)src)[2 * i];
    float4 x1 = ((const float4*)src)[2 * i + 1];
    uint4 h;
    h.x = pack_h2(x0.x, x0.y);
    h.y = pack_h2(x0.z, x0.w);
    h.z = pack_h2(x1.x, x1.y);
    h.w = pack_h2(x1.z, x1.w);
    ((uint4*)dst)[i] = h;
}

// ---------------- main fused attention ----------------
__global__ void __launch_bounds__(NT, 2)
attn_tc_kernel(const float* __restrict__ q,
               const float* __restrict__ mask,
               float* __restrict__ out_o,
               float* __restrict__ out_attn)
{
    extern __shared__ char smc[];
    float* mc = (float*)(smc + OFF_MC);
    float (*rsp)[2] = (float (*)[2])(smc + OFF_RS);
    float* rinv = (float*)(smc + OFF_RI);
    float* Ob = (float*)smc;              // reuses stages after the loop
    __half* Qs = (__half*)(smc + OFF_Q);

    const int bh  = blockIdx.y;
    const int i0  = blockIdx.x * TI;
    const int b   = bh >> 3;              // H = 8
    const int tid = threadIdx.x;
    const int L   = tid & 31;
    const int w   = tid >> 5;             // warp 0..7
    const int wi  = w & 3;                // 16-row group
    const int wj  = w >> 2;               // 0..1 -> 32-col (=k) group
    const int g   = L >> 2;
    const int t   = L & 3;

    const uint32_t smB = smem_u32(smc);
    const uint32_t qB = smB + OFF_Q;

    const __half* k_b = g_k + (size_t)bh * LEN * DIM;
    const __half* v_b = g_v + (size_t)bh * LEN * DIM;

    // per-thread cp.async addressing for K/V tiles (64 rows x 128B, PB pitch)
    const int cprow0 = tid >> 3;              // rows tid/8 and tid/8+32
    const int cpch   = (tid & 7) * 8;
    const uint32_t cpdoff0 = (uint32_t)(cprow0 * PB + cpch) * 2;
    const uint32_t cpdoff1 = (uint32_t)((cprow0 + 32) * PB + cpch) * 2;

    // issue tile 0 into stage 0 first (loads fly under Q convert below)
    {
        int soff0 = cprow0 * DIM + cpch;
        int soff1 = (cprow0 + 32) * DIM + cpch;
        uint32_t s0 = smB;
        CP16(s0 + cpdoff0,        k_b + soff0);
        CP16(s0 + cpdoff1,        k_b + soff1);
        CP16(s0 + 9216 + cpdoff0, v_b + soff0);
        CP16(s0 + 9216 + cpdoff1, v_b + soff1);
        CP_COMMIT();
    }

    // column mask term: 0 or 1e9
    for (int j = tid; j < LEN; j += NT) {
        float mv = mask[b * LEN + j];
        mc[j] = (mv == -10000.0f) ? 1e9f : mv;
    }

    // inline Q convert: 64x64 fp32 -> fp16 in smem
    {
        const float* qb = q + ((size_t)bh * LEN + i0) * DIM;
        #pragma unroll
        for (int it = 0; it < 4; it++) {
            int lin = it * NT + tid;             // 0..1023 float4 chunks
            int row = lin >> 4;
            int c4  = (lin & 15) * 4;
            float4 x = *(const float4*)(qb + row * DIM + c4);
            *(uint32_t*)&Qs[row * PB + c4]     = pack_h2(x.x, x.y);
            *(uint32_t*)&Qs[row * PB + c4 + 2] = pack_h2(x.z, x.w);
        }
    }
    CP_WAIT0();
    __syncthreads();

    float oacc[8][4];
    #pragma unroll
    for (int n = 0; n < 8; n++)
        #pragma unroll
        for (int c = 0; c < 4; c++) oacc[n][c] = 0.0f;
    float rs0 = 0.0f, rs1 = 0.0f;

    const int r0l = wi * 16 + g;
    const int r1l = r0l + 8;

    // addressing
    const int arow = wi * 16 + (L & 15);
    const int acol = (L >> 4) * 8;
    const int b1rowb = wj * 32 + ((L >> 4) & 1) * 8 + (L & 7);
    const int b1col  = ((L >> 3) & 1) * 8;
    const int b2rowb = wj * 32 + ((L >> 3) & 1) * 8 + (L & 7);
    const int b2colh = (L >> 4) * 8;

    // persistent Q fragments (fp16; Q smem never overwritten during the loop)
    uint32_t qa_p[4][4];
    #pragma unroll
    for (int ks = 0; ks < 4; ks++)
        ldsm4(qa_p[ks], qB + (uint32_t)(arow * PB + ks * 16 + acol) * 2);

    const bool rowM0 = (mc[i0 + r0l] != 0.0f);
    const bool rowM1 = (mc[i0 + r1l] != 0.0f);

    float* ab = out_attn ? out_attn + ((size_t)bh * LEN + i0) * LEN : nullptr;

    for (int jt = 0; jt < NJT; jt++) {
        const uint32_t stB = smB + (uint32_t)(jt & 1) * STAGE_BYTES;

        // prefetch next tile into the other stage
        if (jt + 1 < NJT) {
            const int j1 = (jt + 1) * 64;
            uint32_t s1 = smB + (uint32_t)((jt + 1) & 1) * STAGE_BYTES;
            int soff0 = (j1 + cprow0) * DIM + cpch;
            int soff1 = (j1 + cprow0 + 32) * DIM + cpch;
            CP16(s1 + cpdoff0,        k_b + soff0);
            CP16(s1 + cpdoff1,        k_b + soff1);
            CP16(s1 + 9216 + cpdoff0, v_b + soff0);
            CP16(s1 + 9216 + cpdoff1, v_b + soff1);
            CP_COMMIT();
        }

        // ---- GEMM1: S(16x32 per warp) = Q.K^T, single-pass fp16 ----
        float sacc[4][4];
        #pragma unroll
        for (int n = 0; n < 4; n++)
            #pragma unroll
            for (int c = 0; c < 4; c++) sacc[n][c] = 0.0f;

        #pragma unroll
        for (int ks = 0; ks < 4; ks++) {
            #pragma unroll
            for (int jb = 0; jb < 2; jb++) {
                uint32_t addr = stB + (uint32_t)((b1rowb + jb * 16) * PB + ks * 16 + b1col) * 2;
                uint32_t kb4[4];
                ldsm4(kb4, addr);
                mma_f16(sacc[2 * jb],     qa_p[ks], kb4[0], kb4[1]);
                mma_f16(sacc[2 * jb + 1], qa_p[ks], kb4[2], kb4[3]);
            }
        }

        // ---- interleaved epilogue + GEMM2, per 16-k chunk ----
        const int j0 = jt * 64;
        #pragma unroll
        for (int ks2 = 0; ks2 < 2; ks2++) {
            uint32_t ah[4];
            #pragma unroll
            for (int nb2 = 0; nb2 < 2; nb2++) {
                int nb = 2 * ks2 + nb2;
                int lcol = wj * 32 + nb * 8 + 2 * t;
                int jj = j0 + lcol;
                float mj0 = mc[jj], mj1 = mc[jj + 1];
                float u0 = (mj0 == 0.0f) ? 1.0f : 0.0f;
                float u1 = (mj1 == 0.0f) ? 1.0f : 0.0f;
                float e00 = rowM0 ? u0 : __expf(fmaf(sacc[nb][0], 0.125f, -mj0));
                float e01 = rowM0 ? u1 : __expf(fmaf(sacc[nb][1], 0.125f, -mj1));
                float e10 = rowM1 ? u0 : __expf(fmaf(sacc[nb][2], 0.125f, -mj0));
                float e11 = rowM1 ? u1 : __expf(fmaf(sacc[nb][3], 0.125f, -mj1));
                rs0 += e00 + e01;
                rs1 += e10 + e11;
                if (ab) {
                    *(float2*)&ab[(size_t)r0l * LEN + jj] = make_float2(e00, e01);
                    *(float2*)&ab[(size_t)r1l * LEN + jj] = make_float2(e10, e11);
                }
                ah[2 * nb2]     = pack_h2(e00, e01);
                ah[2 * nb2 + 1] = pack_h2(e10, e11);
            }
            #pragma unroll
            for (int dc = 0; dc < 4; dc++) {
                uint32_t vaddr = stB + 9216 +
                    (uint32_t)((b2rowb + ks2 * 16) * PB + dc * 16 + b2colh) * 2;
                uint32_t vb4[4];
                ldsm4t(vb4, vaddr);
                mma_f16(oacc[2 * dc],     ah, vb4[0], vb4[1]);
                mma_f16(oacc[2 * dc + 1], ah, vb4[2], vb4[3]);
            }
        }

        CP_WAIT0();       // next tile's loads done (overlapped with compute)
        __syncthreads();  // all warps done with this stage
    }

    // ---- rowsum reduction across t-lanes then across the 2 wj groups ----
    rs0 += __shfl_xor_sync(0xffffffffu, rs0, 1);
    rs0 += __shfl_xor_sync(0xffffffffu, rs0, 2);
    rs1 += __shfl_xor_sync(0xffffffffu, rs1, 1);
    rs1 += __shfl_xor_sync(0xffffffffu, rs1, 2);
    if (t == 0) {
        rsp[r0l][wj] = rs0;
        rsp[r1l][wj] = rs1;
    }
    // dump partial O into the (now dead) stage region
    #pragma unroll
    for (int nb = 0; nb < 8; nb++) {
        int col = nb * 8 + 2 * t;
        *(float2*)&Ob[wj * (64 * OBP) + r0l * OBP + col] = make_float2(oacc[nb][0], oacc[nb][1]);
        *(float2*)&Ob[wj * (64 * OBP) + r1l * OBP + col] = make_float2(oacc[nb][2], oacc[nb][3]);
    }
    __syncthreads();

    if (tid < TI)
        rinv[tid] = 1.0f / (rsp[tid][0] + rsp[tid][1]);
    __syncthreads();

    // ---- O reduce across 2 k-slices + write ----
    if (out_o) {
        #pragma unroll
        for (int rr = 0; rr < 2; rr++) {
            int row = rr * 32 + (tid >> 3);
            int c8  = (tid & 7) * 8;
            float s[8];
            #pragma unroll
            for (int i = 0; i < 8; i++)
                s[i] = Ob[row * OBP + c8 + i] + Ob[64 * OBP + row * OBP + c8 + i];
            float inv = rinv[row];
            float* ob = out_o + ((size_t)bh * LEN + i0 + row) * DIM + c8;
            *(float4*)ob       = make_float4(s[0] * inv, s[1] * inv, s[2] * inv, s[3] * inv);
            *(float4*)(ob + 4) = make_float4(s[4] * inv, s[5] * inv, s[6] * inv, s[7] * inv);
        }
    }

    // ---- normalize attn in place (CTA just wrote it; L2-hot) ----
    if (ab) {
        #pragma unroll 4
        for (int i4 = tid; i4 < TI * (LEN / 4); i4 += NT) {
            int row = i4 >> 7;
            int col = (i4 & 127) * 4;
            float inv = rinv[row];
            float4 e = *(const float4*)&ab[(size_t)row * LEN + col];
            e.x *= inv; e.y *= inv; e.z *= inv; e.w *= inv;
            *(float4*)&ab[(size_t)row * LEN + col] = e;
        }
    }
}

extern "C" void kernel_launch(void* const* d_in, const int* in_sizes, int n_in,
                              void* d_out, int out_size)
{
    const float* q    = (const float*)d_in[0];
    const float* k    = (const float*)d_in[1];
    const float* v    = (const float*)d_in[2];
    const float* mask = (const float*)d_in[3];

    const long long O_ELEMS = (long long)BH * LEN * DIM;   // 4194304
    const long long A_ELEMS = (long long)BH * LEN * LEN;   // 33554432

    float* out = (float*)d_out;
    float* o_ptr = nullptr;
    float* a_ptr = nullptr;
    if ((long long)out_size >= O_ELEMS + A_ELEMS) {
        o_ptr = out;
        a_ptr = out + O_ELEMS;
    } else if ((long long)out_size == A_ELEMS) {
        a_ptr = out;
    } else {
        o_ptr = out;
    }

    dim3 cgrid(NELEM / 8 / 256, 2);
    cvt_kernel<<<cgrid, 256>>>(k, v);

    cudaFuncSetAttribute(attn_tc_kernel,
                         cudaFuncAttributeMaxDynamicSharedMemorySize, SMEM_BYTES);

    dim3 grid(LEN / TI, BH);   // (8, 128) = 1024 CTAs
    attn_tc_kernel<<<grid, NT, SMEM_BYTES>>>(q, mask, o_ptr, a_ptr);
}

// round 14
// speedup vs baseline: 1.6185x; 1.0742x over previous
#include <cuda_runtime.h>
#include <cuda_fp16.h>
#include <cstdint>
#include <cstddef>

// Problem constants: B=16, H=8, L=512, D=64
#define BH   128
#define LEN  512
#define DIM  64
#define TI   64          // q-rows per CTA
#define NT   256         // 8 warps: 4 row-groups (wi) x 2 k-groups (wj)
#define NJT  8           // 512/64 j-tiles
#define NSTG 4           // pipeline stages
#define PB   72          // fp16 smem pitch (144B rows)
#define NELEM (BH*LEN*DIM)

// smem layout (bytes)
// stage s (s=0..3) at s*STAGE_BYTES: K +0 (9216), V +9216
#define STAGE_BYTES 18432
#define OFF_Q   73728            // Q fp16: 64 x 72 = 9216 B
#define OFF_MC  82944            // 512 f32
#define OFF_RS  84992            // 64 x 2 f32
#define OFF_RI  85504            // 64 f32
#define OFF_MB  85760            // 8 mbarriers (full[0..3], empty[0..3])
#define SMEM_BYTES 85824
// O-reduction buffer reuses dead stage region after the loop: 2*64*66*4 = 33792 B
#define OBP 66

// fp16 scratch for K and V (written by prologue kernel)
__device__ __half g_k[NELEM];
__device__ __half g_v[NELEM];

__device__ __forceinline__ uint32_t smem_u32(const void* p) {
    return (uint32_t)__cvta_generic_to_shared(p);
}
__device__ __forceinline__ void ldsm4(uint32_t* r, uint32_t a) {
    asm volatile("ldmatrix.sync.aligned.m8n8.x4.shared.b16 {%0,%1,%2,%3}, [%4];"
                 : "=r"(r[0]), "=r"(r[1]), "=r"(r[2]), "=r"(r[3]) : "r"(a));
}
__device__ __forceinline__ void ldsm4t(uint32_t* r, uint32_t a) {
    asm volatile("ldmatrix.sync.aligned.m8n8.x4.trans.shared.b16 {%0,%1,%2,%3}, [%4];"
                 : "=r"(r[0]), "=r"(r[1]), "=r"(r[2]), "=r"(r[3]) : "r"(a));
}
__device__ __forceinline__ void mma_f16(float* c, const uint32_t* a, uint32_t b0, uint32_t b1) {
    asm volatile("mma.sync.aligned.m16n8k16.row.col.f32.f16.f16.f32 "
                 "{%0,%1,%2,%3}, {%4,%5,%6,%7}, {%8,%9}, {%0,%1,%2,%3};"
                 : "+f"(c[0]), "+f"(c[1]), "+f"(c[2]), "+f"(c[3])
                 : "r"(a[0]), "r"(a[1]), "r"(a[2]), "r"(a[3]), "r"(b0), "r"(b1));
}
__device__ __forceinline__ uint32_t pack_h2(float x0, float x1) {
    __half2 h = __floats2half2_rn(x0, x1);
    return *reinterpret_cast<uint32_t*>(&h);
}
#define CP16(dst, src) \
    asm volatile("cp.async.cg.shared.global [%0], [%1], 16;" :: "r"(dst), "l"(src))
#define CPA_MBAR_ARRIVE(mb) \
    asm volatile("cp.async.mbarrier.arrive.noinc.shared.b64 [%0];" :: "r"((uint32_t)(mb)) : "memory")
#define MBARRIER_INIT(mb, n) \
    asm volatile("mbarrier.init.shared.b64 [%0], %1;" :: "r"((uint32_t)(mb)), "r"((uint32_t)(n)) : "memory")
#define MBARRIER_ARRIVE(mb) \
    asm volatile("mbarrier.arrive.shared.b64 _, [%0];" :: "r"((uint32_t)(mb)) : "memory")
#define MBARRIER_WAIT_PARITY(mb, ph) do { \
    uint32_t _mb = (uint32_t)(mb), _ph = (uint32_t)(ph), _done; \
    asm volatile("{\n\t.reg .pred p;\n\t" \
        "mbarrier.try_wait.parity.acquire.cta.shared::cta.b64 p, [%1], %2;\n\t" \
        "selp.b32 %0, 1, 0, p;\n\t}" : "=r"(_done) : "r"(_mb), "r"(_ph) : "memory"); \
    if (!_done) { \
        asm volatile("{\n\t.reg .pred P1;\n\t" \
            "WL_%=:\n\t" \
            "mbarrier.try_wait.parity.acquire.cta.shared::cta.b64 P1, [%0], %1, 0x989680;\n\t" \
            "@P1 bra.uni WD_%=;\n\t" \
            "bra.uni WL_%=;\n\t" \
            "WD_%=:\n\t}" :: "r"(_mb), "r"(_ph) : "memory"); \
    } \
} while (0)

// ---------------- prologue: fp32 -> fp16 convert (K and V) ----------------
__global__ void __launch_bounds__(256)
cvt_kernel(const float* __restrict__ k,
           const float* __restrict__ v)
{
    const float* src = (blockIdx.y == 0) ? k : v;
    __half* dst = (blockIdx.y == 0) ? g_k : g_v;

    int i = blockIdx.x * 256 + threadIdx.x;       // 8-float chunk index
    float4 x0 = ((const float4*)src)[2 * i];
    float4 x1 = ((const float4*)src)[2 * i + 1];
    uint4 h;
    h.x = pack_h2(x0.x, x0.y);
    h.y = pack_h2(x0.z, x0.w);
    h.z = pack_h2(x1.x, x1.y);
    h.w = pack_h2(x1.z, x1.w);
    ((uint4*)dst)[i] = h;
}

// ---------------- main fused attention ----------------
__global__ void __launch_bounds__(NT, 2)
attn_tc_kernel(const float* __restrict__ q,
               const float* __restrict__ mask,
               float* __restrict__ out_o,
               float* __restrict__ out_attn)
{
    extern __shared__ char smc[];
    float* mc = (float*)(smc + OFF_MC);
    float (*rsp)[2] = (float (*)[2])(smc + OFF_RS);
    float* rinv = (float*)(smc + OFF_RI);
    float* Ob = (float*)smc;              // reuses stages after the loop
    __half* Qs = (__half*)(smc + OFF_Q);

    const int bh  = blockIdx.y;
    const int i0  = blockIdx.x * TI;
    const int b   = bh >> 3;              // H = 8
    const int tid = threadIdx.x;
    const int L   = tid & 31;
    const int w   = tid >> 5;             // warp 0..7
    const int wi  = w & 3;                // 16-row group
    const int wj  = w >> 2;               // 0..1 -> 32-col (=k) group
    const int g   = L >> 2;
    const int t   = L & 3;

    const uint32_t smB = smem_u32(smc);
    const uint32_t qB  = smB + OFF_Q;
    const uint32_t mbF = smB + OFF_MB;       // full[0..3]
    const uint32_t mbE = smB + OFF_MB + 32;  // empty[0..3]

    const __half* k_b = g_k + (size_t)bh * LEN * DIM;
    const __half* v_b = g_v + (size_t)bh * LEN * DIM;

    // per-thread cp.async addressing for K/V tiles (64 rows x 128B, PB pitch)
    const int cprow0 = tid >> 3;              // rows tid/8 and tid/8+32
    const int cpch   = (tid & 7) * 8;
    const uint32_t cpdoff0 = (uint32_t)(cprow0 * PB + cpch) * 2;
    const uint32_t cpdoff1 = (uint32_t)((cprow0 + 32) * PB + cpch) * 2;

    // init pipeline mbarriers (full: 256 cp-arrives; empty: 256 thread arrives)
    if (tid < NSTG) {
        MBARRIER_INIT(mbF + tid * 8, NT);
        MBARRIER_INIT(mbE + tid * 8, NT);
    }
    __syncthreads();

    // issue tiles 0 and 1 into stages 0,1
    #pragma unroll
    for (int p = 0; p < 2; p++) {
        uint32_t sB = smB + (uint32_t)p * STAGE_BYTES;
        int j0 = p * 64;
        int soff0 = (j0 + cprow0) * DIM + cpch;
        int soff1 = (j0 + cprow0 + 32) * DIM + cpch;
        CP16(sB + cpdoff0,        k_b + soff0);
        CP16(sB + cpdoff1,        k_b + soff1);
        CP16(sB + 9216 + cpdoff0, v_b + soff0);
        CP16(sB + 9216 + cpdoff1, v_b + soff1);
        CPA_MBAR_ARRIVE(mbF + p * 8);
    }

    // column mask term: 0 or 1e9
    for (int j = tid; j < LEN; j += NT) {
        float mv = mask[b * LEN + j];
        mc[j] = (mv == -10000.0f) ? 1e9f : mv;
    }

    // inline Q convert: 64x64 fp32 -> fp16 in smem
    {
        const float* qb = q + ((size_t)bh * LEN + i0) * DIM;
        #pragma unroll
        for (int it = 0; it < 4; it++) {
            int lin = it * NT + tid;             // 0..1023 float4 chunks
            int row = lin >> 4;
            int c4  = (lin & 15) * 4;
            float4 x = *(const float4*)(qb + row * DIM + c4);
            *(uint32_t*)&Qs[row * PB + c4]     = pack_h2(x.x, x.y);
            *(uint32_t*)&Qs[row * PB + c4 + 2] = pack_h2(x.z, x.w);
        }
    }
    __syncthreads();   // Q + mask visible to all warps

    float oacc[8][4];
    #pragma unroll
    for (int n = 0; n < 8; n++)
        #pragma unroll
        for (int c = 0; c < 4; c++) oacc[n][c] = 0.0f;
    float rs0 = 0.0f, rs1 = 0.0f;

    const int r0l = wi * 16 + g;
    const int r1l = r0l + 8;

    // addressing
    const int arow = wi * 16 + (L & 15);
    const int acol = (L >> 4) * 8;
    const int b1rowb = wj * 32 + ((L >> 4) & 1) * 8 + (L & 7);
    const int b1col  = ((L >> 3) & 1) * 8;
    const int b2rowb = wj * 32 + ((L >> 3) & 1) * 8 + (L & 7);
    const int b2colh = (L >> 4) * 8;

    // persistent Q fragments (fp16; Q smem never overwritten during the loop)
    uint32_t qa_p[4][4];
    #pragma unroll
    for (int ks = 0; ks < 4; ks++)
        ldsm4(qa_p[ks], qB + (uint32_t)(arow * PB + ks * 16 + acol) * 2);

    const bool rowM0 = (mc[i0 + r0l] != 0.0f);
    const bool rowM1 = (mc[i0 + r1l] != 0.0f);

    float* ab = out_attn ? out_attn + ((size_t)bh * LEN + i0) * LEN : nullptr;

    for (int jt = 0; jt < NJT; jt++) {
        // producer: issue tile jt+2 into stage (jt+2)&3
        const int nx = jt + 2;
        if (nx < NJT) {
            const int ns = nx & 3;
            if (nx >= NSTG)   // stage was used by tile nx-4; wait all consumed
                MBARRIER_WAIT_PARITY(mbE + ns * 8, 0);
            uint32_t sB = smB + (uint32_t)ns * STAGE_BYTES;
            int j1 = nx * 64;
            int soff0 = (j1 + cprow0) * DIM + cpch;
            int soff1 = (j1 + cprow0 + 32) * DIM + cpch;
            CP16(sB + cpdoff0,        k_b + soff0);
            CP16(sB + cpdoff1,        k_b + soff1);
            CP16(sB + 9216 + cpdoff0, v_b + soff0);
            CP16(sB + 9216 + cpdoff1, v_b + soff1);
            CPA_MBAR_ARRIVE(mbF + ns * 8);
        }

        // consumer: wait tile jt's data
        const int st = jt & 3;
        MBARRIER_WAIT_PARITY(mbF + st * 8, (jt >> 2) & 1);
        const uint32_t stB = smB + (uint32_t)st * STAGE_BYTES;

        // ---- GEMM1: S(16x32 per warp) = Q.K^T, single-pass fp16 ----
        float sacc[4][4];
        #pragma unroll
        for (int n = 0; n < 4; n++)
            #pragma unroll
            for (int c = 0; c < 4; c++) sacc[n][c] = 0.0f;

        #pragma unroll
        for (int ks = 0; ks < 4; ks++) {
            #pragma unroll
            for (int jb = 0; jb < 2; jb++) {
                uint32_t addr = stB + (uint32_t)((b1rowb + jb * 16) * PB + ks * 16 + b1col) * 2;
                uint32_t kb4[4];
                ldsm4(kb4, addr);
                mma_f16(sacc[2 * jb],     qa_p[ks], kb4[0], kb4[1]);
                mma_f16(sacc[2 * jb + 1], qa_p[ks], kb4[2], kb4[3]);
            }
        }

        // ---- interleaved epilogue + GEMM2, per 16-k chunk ----
        const int j0 = jt * 64;
        #pragma unroll
        for (int ks2 = 0; ks2 < 2; ks2++) {
            uint32_t ah[4];
            #pragma unroll
            for (int nb2 = 0; nb2 < 2; nb2++) {
                int nb = 2 * ks2 + nb2;
                int lcol = wj * 32 + nb * 8 + 2 * t;
                int jj = j0 + lcol;
                float mj0 = mc[jj], mj1 = mc[jj + 1];
                float u0 = (mj0 == 0.0f) ? 1.0f : 0.0f;
                float u1 = (mj1 == 0.0f) ? 1.0f : 0.0f;
                float e00 = rowM0 ? u0 : __expf(fmaf(sacc[nb][0], 0.125f, -mj0));
                float e01 = rowM0 ? u1 : __expf(fmaf(sacc[nb][1], 0.125f, -mj1));
                float e10 = rowM1 ? u0 : __expf(fmaf(sacc[nb][2], 0.125f, -mj0));
                float e11 = rowM1 ? u1 : __expf(fmaf(sacc[nb][3], 0.125f, -mj1));
                rs0 += e00 + e01;
                rs1 += e10 + e11;
                if (ab) {
                    *(float2*)&ab[(size_t)r0l * LEN + jj] = make_float2(e00, e01);
                    *(float2*)&ab[(size_t)r1l * LEN + jj] = make_float2(e10, e11);
                }
                ah[2 * nb2]     = pack_h2(e00, e01);
                ah[2 * nb2 + 1] = pack_h2(e10, e11);
            }
            #pragma unroll
            for (int dc = 0; dc < 4; dc++) {
                uint32_t vaddr = stB + 9216 +
                    (uint32_t)((b2rowb + ks2 * 16) * PB + dc * 16 + b2colh) * 2;
                uint32_t vb4[4];
                ldsm4t(vb4, vaddr);
                mma_f16(oacc[2 * dc],     ah, vb4[0], vb4[1]);
                mma_f16(oacc[2 * dc + 1], ah, vb4[2], vb4[3]);
            }
        }

        // done reading stage jt&3
        MBARRIER_ARRIVE(mbE + st * 8);
    }

    // ---- rowsum reduction across t-lanes then across the 2 wj groups ----
    rs0 += __shfl_xor_sync(0xffffffffu, rs0, 1);
    rs0 += __shfl_xor_sync(0xffffffffu, rs0, 2);
    rs1 += __shfl_xor_sync(0xffffffffu, rs1, 1);
    rs1 += __shfl_xor_sync(0xffffffffu, rs1, 2);
    __syncthreads();   // all warps past the loop; stage smem now dead
    if (t == 0) {
        rsp[r0l][wj] = rs0;
        rsp[r1l][wj] = rs1;
    }
    // dump partial O into the (now dead) stage region
    #pragma unroll
    for (int nb = 0; nb < 8; nb++) {
        int col = nb * 8 + 2 * t;
        *(float2*)&Ob[wj * (64 * OBP) + r0l * OBP + col] = make_float2(oacc[nb][0], oacc[nb][1]);
        *(float2*)&Ob[wj * (64 * OBP) + r1l * OBP + col] = make_float2(oacc[nb][2], oacc[nb][3]);
    }
    __syncthreads();

    if (tid < TI)
        rinv[tid] = 1.0f / (rsp[tid][0] + rsp[tid][1]);
    __syncthreads();

    // ---- O reduce across 2 k-slices + write ----
    if (out_o) {
        #pragma unroll
        for (int rr = 0; rr < 2; rr++) {
            int row = rr * 32 + (tid >> 3);
            int c8  = (tid & 7) * 8;
            float s[8];
            #pragma unroll
            for (int i = 0; i < 8; i++)
                s[i] = Ob[row * OBP + c8 + i] + Ob[64 * OBP + row * OBP + c8 + i];
            float inv = rinv[row];
            float* ob = out_o + ((size_t)bh * LEN + i0 + row) * DIM + c8;
            *(float4*)ob       = make_float4(s[0] * inv, s[1] * inv, s[2] * inv, s[3] * inv);
            *(float4*)(ob + 4) = make_float4(s[4] * inv, s[5] * inv, s[6] * inv, s[7] * inv);
        }
    }

    // ---- normalize attn in place (CTA just wrote it; L2-hot) ----
    if (ab) {
        #pragma unroll 4
        for (int i4 = tid; i4 < TI * (LEN / 4); i4 += NT) {
            int row = i4 >> 7;
            int col = (i4 & 127) * 4;
            float inv = rinv[row];
            float4 e = *(const float4*)&ab[(size_t)row * LEN + col];
            e.x *= inv; e.y *= inv; e.z *= inv; e.w *= inv;
            *(float4*)&ab[(size_t)row * LEN + col] = e;
        }
    }
}

extern "C" void kernel_launch(void* const* d_in, const int* in_sizes, int n_in,
                              void* d_out, int out_size)
{
    const float* q    = (const float*)d_in[0];
    const float* k    = (const float*)d_in[1];
    const float* v    = (const float*)d_in[2];
    const float* mask = (const float*)d_in[3];

    const long long O_ELEMS = (long long)BH * LEN * DIM;   // 4194304
    const long long A_ELEMS = (long long)BH * LEN * LEN;   // 33554432

    float* out = (float*)d_out;
    float* o_ptr = nullptr;
    float* a_ptr = nullptr;
    if ((long long)out_size >= O_ELEMS + A_ELEMS) {
        o_ptr = out;
        a_ptr = out + O_ELEMS;
    } else if ((long long)out_size == A_ELEMS) {
        a_ptr = out;
    } else {
        o_ptr = out;
    }

    dim3 cgrid(NELEM / 8 / 256, 2);
    cvt_kernel<<<cgrid, 256>>>(k, v);

    cudaFuncSetAttribute(attn_tc_kernel,
                         cudaFuncAttributeMaxDynamicSharedMemorySize, SMEM_BYTES);

    dim3 grid(LEN / TI, BH);   // (8, 128) = 1024 CTAs
    attn_tc_kernel<<<grid, NT, SMEM_BYTES>>>(q, mask, o_ptr, a_ptr);
}

// round 15
// speedup vs baseline: 1.9904x; 1.2298x over previous
#include <cuda_runtime.h>
#include <cuda_fp16.h>
#include <cstdint>
#include <cstddef>

// Problem constants: B=16, H=8, L=512, D=64
#define BH   128
#define LEN  512
#define DIM  64
#define TI   64          // q-rows per CTA
#define NT   256         // 8 warps: 4 row-groups (wi) x 2 k-groups (wj)
#define NJT  8           // 512/64 j-tiles
#define NSTG 2           // pipeline stages
#define PB   72          // fp16 smem pitch for Q/K/V tiles (144B rows)
#define PEH  520         // fp16 smem pitch for E rows (conflict-free STS)
#define NELEM (BH*LEN*DIM)

// smem layout (bytes)
// stage s (s=0,1) at s*STAGE_BYTES: K +0 (9216), V +9216
#define STAGE_BYTES 18432
#define OFF_E   36864            // E fp16: 64 x 520 x 2 = 66560 B (Q staged here pre-loop)
#define OFF_MC  103424           // 512 f32
#define OFF_RS  105472           // 64 x 2 f32
#define OFF_RI  105984           // 64 f32
#define OFF_MB  106240           // mbarriers full[0..1], empty[0..1]
#define SMEM_BYTES 106304
// O-reduction buffer reuses dead stage region after the loop: 2*64*66*4 = 33792 B
#define OBP 66

// fp16 scratch for K and V (written by prologue kernel)
__device__ __half g_k[NELEM];
__device__ __half g_v[NELEM];

__device__ __forceinline__ uint32_t smem_u32(const void* p) {
    return (uint32_t)__cvta_generic_to_shared(p);
}
__device__ __forceinline__ void ldsm4(uint32_t* r, uint32_t a) {
    asm volatile("ldmatrix.sync.aligned.m8n8.x4.shared.b16 {%0,%1,%2,%3}, [%4];"
                 : "=r"(r[0]), "=r"(r[1]), "=r"(r[2]), "=r"(r[3]) : "r"(a));
}
__device__ __forceinline__ void ldsm4t(uint32_t* r, uint32_t a) {
    asm volatile("ldmatrix.sync.aligned.m8n8.x4.trans.shared.b16 {%0,%1,%2,%3}, [%4];"
                 : "=r"(r[0]), "=r"(r[1]), "=r"(r[2]), "=r"(r[3]) : "r"(a));
}
__device__ __forceinline__ void mma_f16(float* c, const uint32_t* a, uint32_t b0, uint32_t b1) {
    asm volatile("mma.sync.aligned.m16n8k16.row.col.f32.f16.f16.f32 "
                 "{%0,%1,%2,%3}, {%4,%5,%6,%7}, {%8,%9}, {%0,%1,%2,%3};"
                 : "+f"(c[0]), "+f"(c[1]), "+f"(c[2]), "+f"(c[3])
                 : "r"(a[0]), "r"(a[1]), "r"(a[2]), "r"(a[3]), "r"(b0), "r"(b1));
}
__device__ __forceinline__ uint32_t pack_h2(float x0, float x1) {
    __half2 h = __floats2half2_rn(x0, x1);
    return *reinterpret_cast<uint32_t*>(&h);
}
#define CP16(dst, src) \
    asm volatile("cp.async.cg.shared.global [%0], [%1], 16;" :: "r"(dst), "l"(src))
#define CPA_MBAR_ARRIVE(mb) \
    asm volatile("cp.async.mbarrier.arrive.noinc.shared.b64 [%0];" :: "r"((uint32_t)(mb)) : "memory")
#define MBARRIER_INIT(mb, n) \
    asm volatile("mbarrier.init.shared.b64 [%0], %1;" :: "r"((uint32_t)(mb)), "r"((uint32_t)(n)) : "memory")
#define MBARRIER_ARRIVE(mb) \
    asm volatile("mbarrier.arrive.shared.b64 _, [%0];" :: "r"((uint32_t)(mb)) : "memory")
#define MBARRIER_WAIT_PARITY(mb, ph) do { \
    uint32_t _mb = (uint32_t)(mb), _ph = (uint32_t)(ph), _done; \
    asm volatile("{\n\t.reg .pred p;\n\t" \
        "mbarrier.try_wait.parity.acquire.cta.shared::cta.b64 p, [%1], %2;\n\t" \
        "selp.b32 %0, 1, 0, p;\n\t}" : "=r"(_done) : "r"(_mb), "r"(_ph) : "memory"); \
    if (!_done) { \
        asm volatile("{\n\t.reg .pred P1;\n\t" \
            "WL_%=:\n\t" \
            "mbarrier.try_wait.parity.acquire.cta.shared::cta.b64 P1, [%0], %1, 0x989680;\n\t" \
            "@P1 bra.uni WD_%=;\n\t" \
            "bra.uni WL_%=;\n\t" \
            "WD_%=:\n\t}" :: "r"(_mb), "r"(_ph) : "memory"); \
    } \
} while (0)

// ---------------- prologue: fp32 -> fp16 convert (K and V) ----------------
__global__ void __launch_bounds__(256)
cvt_kernel(const float* __restrict__ k,
           const float* __restrict__ v)
{
    const float* src = (blockIdx.y == 0) ? k : v;
    __half* dst = (blockIdx.y == 0) ? g_k : g_v;

    int i = blockIdx.x * 256 + threadIdx.x;       // 8-float chunk index
    float4 x0 = ((const float4*)src)[2 * i];
    float4 x1 = ((const float4*)src)[2 * i + 1];
    uint4 h;
    h.x = pack_h2(x0.x, x0.y);
    h.y = pack_h2(x0.z, x0.w);
    h.z = pack_h2(x1.x, x1.y);
    h.w = pack_h2(x1.z, x1.w);
    ((uint4*)dst)[i] = h;
}

// ---------------- main fused attention ----------------
__global__ void __launch_bounds__(NT, 2)
attn_tc_kernel(const float* __restrict__ q,
               const float* __restrict__ mask,
               float* __restrict__ out_o,
               float* __restrict__ out_attn)
{
    extern __shared__ char smc[];
    float* mc = (float*)(smc + OFF_MC);
    float (*rsp)[2] = (float (*)[2])(smc + OFF_RS);
    float* rinv = (float*)(smc + OFF_RI);
    float* Ob = (float*)smc;              // reuses stage region after the loop
    __half* Es = (__half*)(smc + OFF_E);  // E fp16 (Q staged here pre-loop)
    __half* Qs = (__half*)(smc + OFF_E);

    const int bh  = blockIdx.y;
    const int i0  = blockIdx.x * TI;
    const int b   = bh >> 3;              // H = 8
    const int tid = threadIdx.x;
    const int L   = tid & 31;
    const int w   = tid >> 5;             // warp 0..7
    const int wi  = w & 3;                // 16-row group
    const int wj  = w >> 2;               // 0..1 -> 32-col (=k) group
    const int g   = L >> 2;
    const int t   = L & 3;

    const uint32_t smB = smem_u32(smc);
    const uint32_t qB  = smB + OFF_E;
    const uint32_t mbF = smB + OFF_MB;       // full[0..1]
    const uint32_t mbE = smB + OFF_MB + 16;  // empty[0..1]

    const __half* k_b = g_k + (size_t)bh * LEN * DIM;
    const __half* v_b = g_v + (size_t)bh * LEN * DIM;

    // per-thread cp.async addressing for K/V tiles (64 rows x 128B, PB pitch)
    const int cprow0 = tid >> 3;              // rows tid/8 and tid/8+32
    const int cpch   = (tid & 7) * 8;
    const uint32_t cpdoff0 = (uint32_t)(cprow0 * PB + cpch) * 2;
    const uint32_t cpdoff1 = (uint32_t)((cprow0 + 32) * PB + cpch) * 2;

    // init pipeline mbarriers
    if (tid < NSTG) {
        MBARRIER_INIT(mbF + tid * 8, NT);
        MBARRIER_INIT(mbE + tid * 8, NT);
    }
    __syncthreads();

    // issue tile 0 into stage 0
    {
        int soff0 = cprow0 * DIM + cpch;
        int soff1 = (cprow0 + 32) * DIM + cpch;
        CP16(smB + cpdoff0,        k_b + soff0);
        CP16(smB + cpdoff1,        k_b + soff1);
        CP16(smB + 9216 + cpdoff0, v_b + soff0);
        CP16(smB + 9216 + cpdoff1, v_b + soff1);
        CPA_MBAR_ARRIVE(mbF);
    }

    // column mask term: 0 or 1e9
    for (int j = tid; j < LEN; j += NT) {
        float mv = mask[b * LEN + j];
        mc[j] = (mv == -10000.0f) ? 1e9f : mv;
    }

    // inline Q convert: 64x64 fp32 -> fp16 in smem (staged in the E region)
    {
        const float* qb = q + ((size_t)bh * LEN + i0) * DIM;
        #pragma unroll
        for (int it = 0; it < 4; it++) {
            int lin = it * NT + tid;             // 0..1023 float4 chunks
            int row = lin >> 4;
            int c4  = (lin & 15) * 4;
            float4 x = *(const float4*)(qb + row * DIM + c4);
            *(uint32_t*)&Qs[row * PB + c4]     = pack_h2(x.x, x.y);
            *(uint32_t*)&Qs[row * PB + c4 + 2] = pack_h2(x.z, x.w);
        }
    }
    __syncthreads();   // Q + mask visible to all warps

    float oacc[8][4];
    #pragma unroll
    for (int n = 0; n < 8; n++)
        #pragma unroll
        for (int c = 0; c < 4; c++) oacc[n][c] = 0.0f;
    float rs0 = 0.0f, rs1 = 0.0f;

    const int r0l = wi * 16 + g;
    const int r1l = r0l + 8;

    // addressing
    const int arow = wi * 16 + (L & 15);
    const int acol = (L >> 4) * 8;
    const int b1rowb = wj * 32 + ((L >> 4) & 1) * 8 + (L & 7);
    const int b1col  = ((L >> 3) & 1) * 8;
    const int b2rowb = wj * 32 + ((L >> 3) & 1) * 8 + (L & 7);
    const int b2colh = (L >> 4) * 8;

    // persistent Q fragments (fp16)
    uint32_t qa_p[4][4];
    #pragma unroll
    for (int ks = 0; ks < 4; ks++)
        ldsm4(qa_p[ks], qB + (uint32_t)(arow * PB + ks * 16 + acol) * 2);

    __syncthreads();   // ALL warps' Q frags loaded before any E write overlays Q

    const bool rowM0 = (mc[i0 + r0l] != 0.0f);
    const bool rowM1 = (mc[i0 + r1l] != 0.0f);

    for (int jt = 0; jt < NJT; jt++) {
        // producer: issue tile jt+1 into stage (jt+1)&1
        const int nx = jt + 1;
        if (nx < NJT) {
            const int ns = nx & 1;
            if (nx >= NSTG)   // stage held tile nx-2; wait for all consumers
                MBARRIER_WAIT_PARITY(mbE + ns * 8, ((nx >> 1) - 1) & 1);
            uint32_t sB = smB + (uint32_t)ns * STAGE_BYTES;
            int j1 = nx * 64;
            int soff0 = (j1 + cprow0) * DIM + cpch;
            int soff1 = (j1 + cprow0 + 32) * DIM + cpch;
            CP16(sB + cpdoff0,        k_b + soff0);
            CP16(sB + cpdoff1,        k_b + soff1);
            CP16(sB + 9216 + cpdoff0, v_b + soff0);
            CP16(sB + 9216 + cpdoff1, v_b + soff1);
            CPA_MBAR_ARRIVE(mbF + ns * 8);
        }

        // consumer: wait tile jt's data
        const int st = jt & 1;
        MBARRIER_WAIT_PARITY(mbF + st * 8, (jt >> 1) & 1);
        const uint32_t stB = smB + (uint32_t)st * STAGE_BYTES;

        // ---- GEMM1: S(16x32 per warp) = Q.K^T, single-pass fp16 ----
        float sacc[4][4];
        #pragma unroll
        for (int n = 0; n < 4; n++)
            #pragma unroll
            for (int c = 0; c < 4; c++) sacc[n][c] = 0.0f;

        #pragma unroll
        for (int ks = 0; ks < 4; ks++) {
            #pragma unroll
            for (int jb = 0; jb < 2; jb++) {
                uint32_t addr = stB + (uint32_t)((b1rowb + jb * 16) * PB + ks * 16 + b1col) * 2;
                uint32_t kb4[4];
                ldsm4(kb4, addr);
                mma_f16(sacc[2 * jb],     qa_p[ks], kb4[0], kb4[1]);
                mma_f16(sacc[2 * jb + 1], qa_p[ks], kb4[2], kb4[3]);
            }
        }

        // ---- interleaved epilogue + GEMM2, per 16-k chunk ----
        const int j0 = jt * 64;
        #pragma unroll
        for (int ks2 = 0; ks2 < 2; ks2++) {
            uint32_t ah[4];
            #pragma unroll
            for (int nb2 = 0; nb2 < 2; nb2++) {
                int nb = 2 * ks2 + nb2;
                int lcol = wj * 32 + nb * 8 + 2 * t;
                int jj = j0 + lcol;
                float mj0 = mc[jj], mj1 = mc[jj + 1];
                float u0 = (mj0 == 0.0f) ? 1.0f : 0.0f;
                float u1 = (mj1 == 0.0f) ? 1.0f : 0.0f;
                float e00 = rowM0 ? u0 : __expf(fmaf(sacc[nb][0], 0.125f, -mj0));
                float e01 = rowM0 ? u1 : __expf(fmaf(sacc[nb][1], 0.125f, -mj1));
                float e10 = rowM1 ? u0 : __expf(fmaf(sacc[nb][2], 0.125f, -mj0));
                float e11 = rowM1 ? u1 : __expf(fmaf(sacc[nb][3], 0.125f, -mj1));
                rs0 += e00 + e01;
                rs1 += e10 + e11;
                uint32_t p0 = pack_h2(e00, e01);
                uint32_t p1 = pack_h2(e10, e11);
                // stash E fp16 in smem (conflict-free: bank = 4g+16wj+4nb+t)
                *(uint32_t*)&Es[r0l * PEH + jj] = p0;
                *(uint32_t*)&Es[r1l * PEH + jj] = p1;
                ah[2 * nb2]     = p0;
                ah[2 * nb2 + 1] = p1;
            }
            #pragma unroll
            for (int dc = 0; dc < 4; dc++) {
                uint32_t vaddr = stB + 9216 +
                    (uint32_t)((b2rowb + ks2 * 16) * PB + dc * 16 + b2colh) * 2;
                uint32_t vb4[4];
                ldsm4t(vb4, vaddr);
                mma_f16(oacc[2 * dc],     ah, vb4[0], vb4[1]);
                mma_f16(oacc[2 * dc + 1], ah, vb4[2], vb4[3]);
            }
        }

        // done reading stage jt&1
        MBARRIER_ARRIVE(mbE + st * 8);
    }

    // ---- rowsum reduction across t-lanes then across the 2 wj groups ----
    rs0 += __shfl_xor_sync(0xffffffffu, rs0, 1);
    rs0 += __shfl_xor_sync(0xffffffffu, rs0, 2);
    rs1 += __shfl_xor_sync(0xffffffffu, rs1, 1);
    rs1 += __shfl_xor_sync(0xffffffffu, rs1, 2);
    __syncthreads();   // all warps past the loop; stage smem now dead
    if (t == 0) {
        rsp[r0l][wj] = rs0;
        rsp[r1l][wj] = rs1;
    }
    // dump partial O into the (now dead) stage region
    #pragma unroll
    for (int nb = 0; nb < 8; nb++) {
        int col = nb * 8 + 2 * t;
        *(float2*)&Ob[wj * (64 * OBP) + r0l * OBP + col] = make_float2(oacc[nb][0], oacc[nb][1]);
        *(float2*)&Ob[wj * (64 * OBP) + r1l * OBP + col] = make_float2(oacc[nb][2], oacc[nb][3]);
    }
    __syncthreads();

    if (tid < TI)
        rinv[tid] = 1.0f / (rsp[tid][0] + rsp[tid][1]);
    __syncthreads();

    // ---- O reduce across 2 k-slices + write ----
    if (out_o) {
        #pragma unroll
        for (int rr = 0; rr < 2; rr++) {
            int row = rr * 32 + (tid >> 3);
            int c8  = (tid & 7) * 8;
            float s[8];
            #pragma unroll
            for (int i = 0; i < 8; i++)
                s[i] = Ob[row * OBP + c8 + i] + Ob[64 * OBP + row * OBP + c8 + i];
            float inv = rinv[row];
            float* ob = out_o + ((size_t)bh * LEN + i0 + row) * DIM + c8;
            *(float4*)ob       = make_float4(s[0] * inv, s[1] * inv, s[2] * inv, s[3] * inv);
            *(float4*)(ob + 4) = make_float4(s[4] * inv, s[5] * inv, s[6] * inv, s[7] * inv);
        }
    }

    // ---- attn: single normalized write from E fp16 smem ----
    if (out_attn) {
        float* abase = out_attn + ((size_t)bh * LEN + i0) * LEN;
        #pragma unroll 4
        for (int i4 = tid; i4 < TI * (LEN / 4); i4 += NT) {
            int row = i4 >> 7;               // 128 float4 per row
            int col = (i4 & 127) * 4;
            float inv = rinv[row];
            __half2 ha = *(__half2*)&Es[row * PEH + col];
            __half2 hb = *(__half2*)&Es[row * PEH + col + 2];
            float2 fa = __half22float2(ha);
            float2 fb = __half22float2(hb);
            *(float4*)&abase[(size_t)row * LEN + col] =
                make_float4(fa.x * inv, fa.y * inv, fb.x * inv, fb.y * inv);
        }
    }
}

extern "C" void kernel_launch(void* const* d_in, const int* in_sizes, int n_in,
                              void* d_out, int out_size)
{
    const float* q    = (const float*)d_in[0];
    const float* k    = (const float*)d_in[1];
    const float* v    = (const float*)d_in[2];
    const float* mask = (const float*)d_in[3];

    const long long O_ELEMS = (long long)BH * LEN * DIM;   // 4194304
    const long long A_ELEMS = (long long)BH * LEN * LEN;   // 33554432

    float* out = (float*)d_out;
    float* o_ptr = nullptr;
    float* a_ptr = nullptr;
    if ((long long)out_size >= O_ELEMS + A_ELEMS) {
        o_ptr = out;
        a_ptr = out + O_ELEMS;
    } else if ((long long)out_size == A_ELEMS) {
        a_ptr = out;
    } else {
        o_ptr = out;
    }

    dim3 cgrid(NELEM / 8 / 256, 2);
    cvt_kernel<<<cgrid, 256>>>(k, v);

    cudaFuncSetAttribute(attn_tc_kernel,
                         cudaFuncAttributeMaxDynamicSharedMemorySize, SMEM_BYTES);

    dim3 grid(LEN / TI, BH);   // (8, 128) = 1024 CTAs
    attn_tc_kernel<<<grid, NT, SMEM_BYTES>>>(q, mask, o_ptr, a_ptr);
}